// round 4
// baseline (speedup 1.0000x reference)
#include <cuda_runtime.h>
#include <cuda_fp16.h>
#include <stdint.h>

#define G       512
#define CDIM    512
#define TILE_M  128
#define THREADS 256

// ---- SMEM layout (dynamic) ----
#define A_STRIDE_B 1040                    // 520 halves per row (8-half pad)
#define SM_A       0                       // 128 x 1040B = 133120
#define SM_B0      133120                  // 64 x 272B  = 17408
#define SM_B1      150528
#define B_STRIDE   272
#define SM_QT      167936                  // float4[512] = 8192
#define SM_CT      176128                  // float[512]  = 2048
#define SM_PTS     178176                  // 128*3 floats = 1536
#define SM_TOTAL   179712

// fp16 image of latents: [b][k][c] row-major (elementwise convert, no transpose)
__device__ __align__(16) unsigned char g_Bprep[4ull * G * CDIM * 2];

__device__ __forceinline__ uint32_t cvta_s(const void* p) {
    return (uint32_t)__cvta_generic_to_shared(const_cast<void*>(p));
}

__device__ __forceinline__ uint32_t pack_h2(float lo, float hi) {
    __half2 h = __floats2half2_rn(lo, hi);
    return *reinterpret_cast<uint32_t*>(&h);
}

__device__ __forceinline__ void ldsm_x4(uint32_t addr, uint32_t* r) {
    asm volatile("ldmatrix.sync.aligned.m8n8.x4.shared.b16 {%0,%1,%2,%3}, [%4];"
                 : "=r"(r[0]), "=r"(r[1]), "=r"(r[2]), "=r"(r[3]) : "r"(addr));
}

__device__ __forceinline__ void ldsm_x4_t(uint32_t addr, uint32_t* r) {
    asm volatile("ldmatrix.sync.aligned.m8n8.x4.trans.shared.b16 {%0,%1,%2,%3}, [%4];"
                 : "=r"(r[0]), "=r"(r[1]), "=r"(r[2]), "=r"(r[3]) : "r"(addr));
}

__device__ __forceinline__ void mma16816(float* d, const uint32_t* a, const uint32_t* b) {
    asm volatile(
        "mma.sync.aligned.m16n8k16.row.col.f32.f16.f16.f32 "
        "{%0,%1,%2,%3}, {%4,%5,%6,%7}, {%8,%9}, {%0,%1,%2,%3};"
        : "+f"(d[0]), "+f"(d[1]), "+f"(d[2]), "+f"(d[3])
        : "r"(a[0]), "r"(a[1]), "r"(a[2]), "r"(a[3]), "r"(b[0]), "r"(b[1]));
}

// ---------- prep: elementwise fp32 -> fp16 convert of latents ----------
__global__ void rbf_prep(const float* __restrict__ lat) {
    int b = blockIdx.y;
    int i = blockIdx.x * blockDim.x + threadIdx.x;          // float4 index, 65536/batch
    const float4* src = (const float4*)(lat + (size_t)b * G * CDIM);
    uint2* dst = (uint2*)(g_Bprep + (size_t)b * G * CDIM * 2);
    float4 v = src[i];
    uint2 o;
    o.x = pack_h2(v.x, v.y);
    o.y = pack_h2(v.z, v.w);
    dst[i] = o;
}

// ---------- main kernel ----------
__global__ void __launch_bounds__(THREADS, 1)
rbf_main(const float* __restrict__ points, const float* __restrict__ eps,
         float* __restrict__ out, int Ntot)
{
    extern __shared__ __align__(1024) unsigned char smem[];
    const uint32_t sbase = cvta_s(smem);
    const int tid  = threadIdx.x;
    const int wid  = tid >> 5;
    const int lane = tid & 31;
    const int b    = blockIdx.y;
    const int n0   = blockIdx.x * TILE_M;
    const unsigned char* Bsrc = g_Bprep + (size_t)b * (G * CDIM * 2);

    // issue cp.async for B slice g (cc = g>>3, kabs = (g&7)*64) into buffer g&1
    auto issue_slice = [&](int g) {
        int cc   = g >> 3;
        int kabs = (g & 7) * 64;
        uint32_t dstbase = sbase + ((g & 1) ? SM_B1 : SM_B0);
        #pragma unroll
        for (int j = 0; j < 4; ++j) {
            int s  = tid + j * THREADS;                      // 1024 slots: 64 rows x 16 chunks
            int r  = s >> 4;
            int ch = s & 15;
            const unsigned char* src = Bsrc + ((size_t)(kabs + r) * CDIM + cc * 128) * 2 + ch * 16;
            uint32_t dst = dstbase + r * B_STRIDE + ch * 16;
            asm volatile("cp.async.cg.shared.global [%0], [%1], 16;" :: "r"(dst), "l"(src));
        }
        asm volatile("cp.async.commit_group;" ::: "memory");
    };

    issue_slice(0);                                          // overlap with A-gen

    // stage points
    {
        const float* psrc = points + ((size_t)b * Ntot + n0) * 3;
        int nfl = min(TILE_M, Ntot - n0) * 3;
        float* stage = (float*)(smem + SM_PTS);
        for (int i = tid; i < TILE_M * 3; i += THREADS)
            stage[i] = (i < nfl) ? psrc[i] : 0.0f;
    }

    // per-g tables: arg = qx*px+qy*py+qz*pz + s*p2 + s*g2, s = -eps^2*log2(e)
    {
        float4* qt = (float4*)(smem + SM_QT);
        float*  ct = (float*)(smem + SM_CT);
        const float LOG2E = 1.4426950408889634f;
        const float step  = 2.0f / 7.0f;
        for (int g = tid; g < G; g += THREADS) {
            float gx = -1.0f + step * (float)(g >> 6);
            float gy = -1.0f + step * (float)((g >> 3) & 7);
            float gz = -1.0f + step * (float)(g & 7);
            float e  = eps[g];
            float s  = -e * e * LOG2E;
            qt[g] = make_float4(-2.0f * s * gx, -2.0f * s * gy, -2.0f * s * gz, s);
            ct[g] = s * (gx * gx + gy * gy + gz * gz);
        }
    }
    __syncthreads();

    // A-gen: thread -> (row = tid&127, khalf = tid>>7), 256 exps -> fp16 SMEM
    {
        const int row   = tid & 127;
        const int kbase = (tid >> 7) * 256;
        const float* stage = (const float*)(smem + SM_PTS);
        float px = stage[row * 3 + 0], py = stage[row * 3 + 1], pz = stage[row * 3 + 2];
        float p2 = px * px + py * py + pz * pz;
        const float4* qt = (const float4*)(smem + SM_QT);
        const float*  ct = (const float*)(smem + SM_CT);
        #pragma unroll 4
        for (int j = 0; j < 32; ++j) {
            float ev[8];
            #pragma unroll
            for (int q = 0; q < 8; ++q) {
                int g = kbase + j * 8 + q;
                float4 qv = qt[g];
                float arg = fmaf(qv.x, px, fmaf(qv.y, py,
                            fmaf(qv.z, pz, fmaf(qv.w, p2, ct[g]))));
                asm("ex2.approx.f32 %0, %1;" : "=f"(ev[q]) : "f"(arg));
            }
            uint4 pk;
            pk.x = pack_h2(ev[0], ev[1]);
            pk.y = pack_h2(ev[2], ev[3]);
            pk.z = pack_h2(ev[4], ev[5]);
            pk.w = pack_h2(ev[6], ev[7]);
            *reinterpret_cast<uint4*>(smem + SM_A + row * A_STRIDE_B + (kbase + j * 8) * 2) = pk;
        }
    }

    const int wm = (wid & 3) * 32;
    const int wn = (wid >> 2) * 64;

    for (int cc = 0; cc < 4; ++cc) {
        float acc[2][8][4];
        #pragma unroll
        for (int tm = 0; tm < 2; ++tm)
            #pragma unroll
            for (int tn = 0; tn < 8; ++tn)
                #pragma unroll
                for (int q = 0; q < 4; ++q)
                    acc[tm][tn][q] = 0.0f;

        for (int kidx = 0; kidx < 8; ++kidx) {
            int g = cc * 8 + kidx;
            if (g < 31) {
                issue_slice(g + 1);
                asm volatile("cp.async.wait_group 1;" ::: "memory");
            } else {
                asm volatile("cp.async.wait_group 0;" ::: "memory");
            }
            __syncthreads();

            uint32_t Bb = sbase + ((g & 1) ? SM_B1 : SM_B0);
            int kabs = kidx * 64;
            #pragma unroll
            for (int kk = 0; kk < 4; ++kk) {
                int krow = kk * 16;
                uint32_t a[2][4];
                #pragma unroll
                for (int tm = 0; tm < 2; ++tm) {
                    uint32_t addr = sbase + SM_A + (wm + tm * 16 + (lane & 15)) * A_STRIDE_B
                                    + (kabs + krow + (lane >> 4) * 8) * 2;
                    ldsm_x4(addr, a[tm]);
                }
                uint32_t bf[4][4];
                #pragma unroll
                for (int tn2 = 0; tn2 < 4; ++tn2) {
                    uint32_t addr = Bb + (krow + (lane & 15)) * B_STRIDE
                                    + (wn + tn2 * 16 + (lane >> 4) * 8) * 2;
                    ldsm_x4_t(addr, bf[tn2]);
                }
                #pragma unroll
                for (int tm = 0; tm < 2; ++tm)
                    #pragma unroll
                    for (int tn = 0; tn < 8; ++tn)
                        mma16816(acc[tm][tn], a[tm], &bf[tn >> 1][(tn & 1) * 2]);
            }
            __syncthreads();
        }

        // epilogue: direct v2 STG (quarter-warp = full 32B sector)
        #pragma unroll
        for (int tm = 0; tm < 2; ++tm) {
            int rbase = n0 + wm + tm * 16 + (lane >> 2);
            #pragma unroll
            for (int half = 0; half < 2; ++half) {
                int r = rbase + half * 8;
                if (r < Ntot) {
                    float* op = out + ((size_t)b * Ntot + r) * CDIM
                                + cc * 128 + wn + (lane & 3) * 2;
                    #pragma unroll
                    for (int tn = 0; tn < 8; ++tn) {
                        float2 v = make_float2(acc[tm][tn][half * 2],
                                               acc[tm][tn][half * 2 + 1]);
                        *reinterpret_cast<float2*>(op + tn * 8) = v;
                    }
                }
            }
        }
    }
}

extern "C" void kernel_launch(void* const* d_in, const int* in_sizes, int n_in,
                              void* d_out, int out_size) {
    const float* points = (const float*)d_in[0];
    const float* lat    = (const float*)d_in[1];
    const float* eps    = (const float*)d_in[2];
    float* out = (float*)d_out;

    int B = in_sizes[1] / (G * CDIM);          // 4
    int N = in_sizes[0] / (3 * B);             // 50000

    cudaFuncSetAttribute(rbf_main, cudaFuncAttributeMaxDynamicSharedMemorySize, SM_TOTAL);

    rbf_prep<<<dim3((G * CDIM / 4) / THREADS, B), THREADS>>>(lat);
    rbf_main<<<dim3((N + TILE_M - 1) / TILE_M, B), THREADS, SM_TOTAL>>>(points, eps, out, N);
}

// round 5
// speedup vs baseline: 1.1071x; 1.1071x over previous
#include <cuda_runtime.h>
#include <cuda_fp16.h>
#include <stdint.h>

#define G       512
#define CDIM    512
#define TILE_M  128
#define THREADS 512

// ---- SMEM layout (dynamic) ----
#define A_STRIDE_B 1040                    // 520 halves per row (8-half pad)
#define SM_A       0                       // 128 x 1040B = 133120
#define B_STRIDE   528                     // 256 halves + 8 pad
#define SM_B0      133120                  // 64 x 528B = 33792
#define SM_B1      166912
#define SM_QT      200704                  // float4[512] = 8192
#define SM_CT      208896                  // float[512]  = 2048
#define SM_PTS     210944                  // 128*3 floats = 1536
#define SM_TOTAL   212480

// fp16 image of latents: [b][k][c] row-major (elementwise convert, no transpose)
__device__ __align__(16) unsigned char g_Bprep[4ull * G * CDIM * 2];

__device__ __forceinline__ uint32_t cvta_s(const void* p) {
    return (uint32_t)__cvta_generic_to_shared(const_cast<void*>(p));
}

__device__ __forceinline__ uint32_t pack_h2(float lo, float hi) {
    __half2 h = __floats2half2_rn(lo, hi);
    return *reinterpret_cast<uint32_t*>(&h);
}

__device__ __forceinline__ void ldsm_x4(uint32_t addr, uint32_t* r) {
    asm volatile("ldmatrix.sync.aligned.m8n8.x4.shared.b16 {%0,%1,%2,%3}, [%4];"
                 : "=r"(r[0]), "=r"(r[1]), "=r"(r[2]), "=r"(r[3]) : "r"(addr));
}

__device__ __forceinline__ void ldsm_x4_t(uint32_t addr, uint32_t* r) {
    asm volatile("ldmatrix.sync.aligned.m8n8.x4.trans.shared.b16 {%0,%1,%2,%3}, [%4];"
                 : "=r"(r[0]), "=r"(r[1]), "=r"(r[2]), "=r"(r[3]) : "r"(addr));
}

__device__ __forceinline__ void mma16816(float* d, const uint32_t* a, const uint32_t* b) {
    asm volatile(
        "mma.sync.aligned.m16n8k16.row.col.f32.f16.f16.f32 "
        "{%0,%1,%2,%3}, {%4,%5,%6,%7}, {%8,%9}, {%0,%1,%2,%3};"
        : "+f"(d[0]), "+f"(d[1]), "+f"(d[2]), "+f"(d[3])
        : "r"(a[0]), "r"(a[1]), "r"(a[2]), "r"(a[3]), "r"(b[0]), "r"(b[1]));
}

// ---------- prep: elementwise fp32 -> fp16 convert of latents ----------
__global__ void rbf_prep(const float* __restrict__ lat) {
    int b = blockIdx.y;
    int i = blockIdx.x * blockDim.x + threadIdx.x;          // float4 index
    const float4* src = (const float4*)(lat + (size_t)b * G * CDIM);
    uint2* dst = (uint2*)(g_Bprep + (size_t)b * G * CDIM * 2);
    float4 v = src[i];
    uint2 o;
    o.x = pack_h2(v.x, v.y);
    o.y = pack_h2(v.z, v.w);
    dst[i] = o;
}

// ---------- main kernel ----------
__global__ void __launch_bounds__(THREADS, 1)
rbf_main(const float* __restrict__ points, const float* __restrict__ eps,
         float* __restrict__ out, int Ntot)
{
    extern __shared__ __align__(1024) unsigned char smem[];
    const uint32_t sbase = cvta_s(smem);
    const int tid  = threadIdx.x;
    const int wid  = tid >> 5;
    const int lane = tid & 31;
    const int b    = blockIdx.y;
    const int n0   = blockIdx.x * TILE_M;
    const unsigned char* Bsrc = g_Bprep + (size_t)b * (G * CDIM * 2);

    // slice g: cc = g>>3 (256-col half), kabs = (g&7)*64; 64 rows x 256 cols = 32KB
    auto issue_slice = [&](int g) {
        int cc   = g >> 3;
        int kabs = (g & 7) * 64;
        uint32_t dstbase = sbase + ((g & 1) ? SM_B1 : SM_B0);
        #pragma unroll
        for (int j = 0; j < 4; ++j) {
            int s  = tid + j * THREADS;                      // 2048 slots: 64 rows x 32 chunks
            int r  = s >> 5;
            int ch = s & 31;
            const unsigned char* src = Bsrc + ((size_t)(kabs + r) * CDIM + cc * 256) * 2 + ch * 16;
            uint32_t dst = dstbase + r * B_STRIDE + ch * 16;
            asm volatile("cp.async.cg.shared.global [%0], [%1], 16;" :: "r"(dst), "l"(src));
        }
        asm volatile("cp.async.commit_group;" ::: "memory");
    };

    issue_slice(0);                                          // overlap with A-gen

    // stage points
    {
        const float* psrc = points + ((size_t)b * Ntot + n0) * 3;
        int nfl = min(TILE_M, Ntot - n0) * 3;
        float* stage = (float*)(smem + SM_PTS);
        for (int i = tid; i < TILE_M * 3; i += THREADS)
            stage[i] = (i < nfl) ? psrc[i] : 0.0f;
    }

    // per-g tables: arg = qx*px+qy*py+qz*pz + s*p2 + s*g2, s = -eps^2*log2(e)
    {
        float4* qt = (float4*)(smem + SM_QT);
        float*  ct = (float*)(smem + SM_CT);
        const float LOG2E = 1.4426950408889634f;
        const float step  = 2.0f / 7.0f;
        for (int g = tid; g < G; g += THREADS) {
            float gx = -1.0f + step * (float)(g >> 6);
            float gy = -1.0f + step * (float)((g >> 3) & 7);
            float gz = -1.0f + step * (float)(g & 7);
            float e  = eps[g];
            float s  = -e * e * LOG2E;
            qt[g] = make_float4(-2.0f * s * gx, -2.0f * s * gy, -2.0f * s * gz, s);
            ct[g] = s * (gx * gx + gy * gy + gz * gz);
        }
    }
    __syncthreads();

    // A-gen: thread -> (row = tid&127, kquarter = tid>>7), 128 exps -> fp16 SMEM
    {
        const int row   = tid & 127;
        const int kbase = (tid >> 7) * 128;
        const float* stage = (const float*)(smem + SM_PTS);
        float px = stage[row * 3 + 0], py = stage[row * 3 + 1], pz = stage[row * 3 + 2];
        float p2 = px * px + py * py + pz * pz;
        const float4* qt = (const float4*)(smem + SM_QT);
        const float*  ct = (const float*)(smem + SM_CT);
        #pragma unroll 4
        for (int j = 0; j < 16; ++j) {
            float ev[8];
            #pragma unroll
            for (int q = 0; q < 8; ++q) {
                int g = kbase + j * 8 + q;
                float4 qv = qt[g];
                float arg = fmaf(qv.x, px, fmaf(qv.y, py,
                            fmaf(qv.z, pz, fmaf(qv.w, p2, ct[g]))));
                asm("ex2.approx.f32 %0, %1;" : "=f"(ev[q]) : "f"(arg));
            }
            uint4 pk;
            pk.x = pack_h2(ev[0], ev[1]);
            pk.y = pack_h2(ev[2], ev[3]);
            pk.z = pack_h2(ev[4], ev[5]);
            pk.w = pack_h2(ev[6], ev[7]);
            *reinterpret_cast<uint4*>(smem + SM_A + row * A_STRIDE_B + (kbase + j * 8) * 2) = pk;
        }
    }

    const int wm = (wid & 3) * 32;        // 4 M-warps
    const int wn = (wid >> 2) * 64;       // 4 N-warps over 256 cols

    for (int cc = 0; cc < 2; ++cc) {
        float acc[2][8][4];
        #pragma unroll
        for (int tm = 0; tm < 2; ++tm)
            #pragma unroll
            for (int tn = 0; tn < 8; ++tn)
                #pragma unroll
                for (int q = 0; q < 4; ++q)
                    acc[tm][tn][q] = 0.0f;

        for (int kidx = 0; kidx < 8; ++kidx) {
            int g = cc * 8 + kidx;
            if (g < 15) {
                issue_slice(g + 1);
                asm volatile("cp.async.wait_group 1;" ::: "memory");
            } else {
                asm volatile("cp.async.wait_group 0;" ::: "memory");
            }
            __syncthreads();

            uint32_t Bb = sbase + ((g & 1) ? SM_B1 : SM_B0);
            int kabs = kidx * 64;
            #pragma unroll
            for (int kk = 0; kk < 4; ++kk) {
                int krow = kk * 16;
                uint32_t a[2][4];
                #pragma unroll
                for (int tm = 0; tm < 2; ++tm) {
                    uint32_t addr = sbase + SM_A + (wm + tm * 16 + (lane & 15)) * A_STRIDE_B
                                    + (kabs + krow + (lane >> 4) * 8) * 2;
                    ldsm_x4(addr, a[tm]);
                }
                uint32_t bf[4][4];
                #pragma unroll
                for (int tn2 = 0; tn2 < 4; ++tn2) {
                    uint32_t addr = Bb + (krow + (lane & 15)) * B_STRIDE
                                    + (wn + tn2 * 16 + (lane >> 4) * 8) * 2;
                    ldsm_x4_t(addr, bf[tn2]);
                }
                #pragma unroll
                for (int tm = 0; tm < 2; ++tm)
                    #pragma unroll
                    for (int tn = 0; tn < 8; ++tn)
                        mma16816(acc[tm][tn], a[tm], &bf[tn >> 1][(tn & 1) * 2]);
            }
            __syncthreads();
        }

        // epilogue: direct v2 STG (quarter-warp = full 32B sector)
        #pragma unroll
        for (int tm = 0; tm < 2; ++tm) {
            int rbase = n0 + wm + tm * 16 + (lane >> 2);
            #pragma unroll
            for (int half = 0; half < 2; ++half) {
                int r = rbase + half * 8;
                if (r < Ntot) {
                    float* op = out + ((size_t)b * Ntot + r) * CDIM
                                + cc * 256 + wn + (lane & 3) * 2;
                    #pragma unroll
                    for (int tn = 0; tn < 8; ++tn) {
                        float2 v = make_float2(acc[tm][tn][half * 2],
                                               acc[tm][tn][half * 2 + 1]);
                        *reinterpret_cast<float2*>(op + tn * 8) = v;
                    }
                }
            }
        }
    }
}

extern "C" void kernel_launch(void* const* d_in, const int* in_sizes, int n_in,
                              void* d_out, int out_size) {
    const float* points = (const float*)d_in[0];
    const float* lat    = (const float*)d_in[1];
    const float* eps    = (const float*)d_in[2];
    float* out = (float*)d_out;

    int B = in_sizes[1] / (G * CDIM);          // 4
    int N = in_sizes[0] / (3 * B);             // 50000

    cudaFuncSetAttribute(rbf_main, cudaFuncAttributeMaxDynamicSharedMemorySize, SM_TOTAL);

    rbf_prep<<<dim3((G * CDIM / 4) / 256, B), 256>>>(lat);
    rbf_main<<<dim3((N + TILE_M - 1) / TILE_M, B), THREADS, SM_TOTAL>>>(points, eps, out, N);
}

// round 6
// speedup vs baseline: 1.1988x; 1.0828x over previous
#include <cuda_runtime.h>
#include <cuda_fp16.h>
#include <stdint.h>

#define G       512
#define CDIM    512
#define TILE_M  64
#define THREADS 256

// ---- SMEM layout (dynamic, per CTA; 2 CTAs/SM) ----
#define A_STRIDE_B 1040                    // 520 halves per row (8-half pad)
#define SM_A       0                       // 64 x 1040B = 66560
#define B_STRIDE   528                     // 256 halves + 8 pad
#define SM_B0      66560                   // 32 x 528B = 16896
#define SM_B1      83456
#define SM_QT      100352                  // float4[512] = 8192
#define SM_CT      108544                  // float[512]  = 2048
#define SM_PTS     110592                  // 64*3 floats = 768
#define SM_TOTAL   111616                  // x2 CTAs = 223232 <= 227KB

// fp16 image of latents: [b][k][c] row-major (elementwise convert, no transpose)
__device__ __align__(16) unsigned char g_Bprep[4ull * G * CDIM * 2];

__device__ __forceinline__ uint32_t cvta_s(const void* p) {
    return (uint32_t)__cvta_generic_to_shared(const_cast<void*>(p));
}

__device__ __forceinline__ uint32_t pack_h2(float lo, float hi) {
    __half2 h = __floats2half2_rn(lo, hi);
    return *reinterpret_cast<uint32_t*>(&h);
}

__device__ __forceinline__ void ldsm_x4(uint32_t addr, uint32_t* r) {
    asm volatile("ldmatrix.sync.aligned.m8n8.x4.shared.b16 {%0,%1,%2,%3}, [%4];"
                 : "=r"(r[0]), "=r"(r[1]), "=r"(r[2]), "=r"(r[3]) : "r"(addr));
}

__device__ __forceinline__ void ldsm_x4_t(uint32_t addr, uint32_t* r) {
    asm volatile("ldmatrix.sync.aligned.m8n8.x4.trans.shared.b16 {%0,%1,%2,%3}, [%4];"
                 : "=r"(r[0]), "=r"(r[1]), "=r"(r[2]), "=r"(r[3]) : "r"(addr));
}

__device__ __forceinline__ void mma16816(float* d, const uint32_t* a, const uint32_t* b) {
    asm volatile(
        "mma.sync.aligned.m16n8k16.row.col.f32.f16.f16.f32 "
        "{%0,%1,%2,%3}, {%4,%5,%6,%7}, {%8,%9}, {%0,%1,%2,%3};"
        : "+f"(d[0]), "+f"(d[1]), "+f"(d[2]), "+f"(d[3])
        : "r"(a[0]), "r"(a[1]), "r"(a[2]), "r"(a[3]), "r"(b[0]), "r"(b[1]));
}

// ---------- prep: elementwise fp32 -> fp16 convert of latents ----------
__global__ void rbf_prep(const float* __restrict__ lat) {
    int b = blockIdx.y;
    int i = blockIdx.x * blockDim.x + threadIdx.x;          // float4 index
    const float4* src = (const float4*)(lat + (size_t)b * G * CDIM);
    uint2* dst = (uint2*)(g_Bprep + (size_t)b * G * CDIM * 2);
    float4 v = src[i];
    uint2 o;
    o.x = pack_h2(v.x, v.y);
    o.y = pack_h2(v.z, v.w);
    dst[i] = o;
}

// ---------- main kernel ----------
__global__ void __launch_bounds__(THREADS, 2)
rbf_main(const float* __restrict__ points, const float* __restrict__ eps,
         float* __restrict__ out, int Ntot)
{
    extern __shared__ __align__(1024) unsigned char smem[];
    const uint32_t sbase = cvta_s(smem);
    const int tid  = threadIdx.x;
    const int wid  = tid >> 5;
    const int lane = tid & 31;
    const int b    = blockIdx.y;
    const int n0   = blockIdx.x * TILE_M;
    const unsigned char* Bsrc = g_Bprep + (size_t)b * (G * CDIM * 2);

    // slice g (0..31): cc = g>>4 (C half), kabs = (g&15)*32; 32 rows x 256 cols = 16.5KB
    auto issue_slice = [&](int g) {
        int cc   = g >> 4;
        int kabs = (g & 15) * 32;
        uint32_t dstbase = sbase + ((g & 1) ? SM_B1 : SM_B0);
        #pragma unroll
        for (int j = 0; j < 4; ++j) {
            int s  = tid + j * THREADS;                      // 1024 slots: 32 rows x 32 chunks
            int r  = s >> 5;
            int ch = s & 31;
            const unsigned char* src = Bsrc + ((size_t)(kabs + r) * CDIM + cc * 256) * 2 + ch * 16;
            uint32_t dst = dstbase + r * B_STRIDE + ch * 16;
            asm volatile("cp.async.cg.shared.global [%0], [%1], 16;" :: "r"(dst), "l"(src));
        }
        asm volatile("cp.async.commit_group;" ::: "memory");
    };

    issue_slice(0);                                          // overlaps A-gen

    // stage points
    {
        const float* psrc = points + ((size_t)b * Ntot + n0) * 3;
        int nfl = min(TILE_M, Ntot - n0) * 3;
        float* stage = (float*)(smem + SM_PTS);
        for (int i = tid; i < TILE_M * 3; i += THREADS)
            stage[i] = (i < nfl) ? psrc[i] : 0.0f;
    }

    // per-g tables: arg = qx*px+qy*py+qz*pz + s*p2 + s*g2, s = -eps^2*log2(e)
    {
        float4* qt = (float4*)(smem + SM_QT);
        float*  ct = (float*)(smem + SM_CT);
        const float LOG2E = 1.4426950408889634f;
        const float step  = 2.0f / 7.0f;
        for (int g = tid; g < G; g += THREADS) {
            float gx = -1.0f + step * (float)(g >> 6);
            float gy = -1.0f + step * (float)((g >> 3) & 7);
            float gz = -1.0f + step * (float)(g & 7);
            float e  = eps[g];
            float s  = -e * e * LOG2E;
            qt[g] = make_float4(-2.0f * s * gx, -2.0f * s * gy, -2.0f * s * gz, s);
            ct[g] = s * (gx * gx + gy * gy + gz * gz);
        }
    }
    __syncthreads();

    // A-gen: thread -> (row = tid&63, kq = tid>>6), 128 exps -> fp16 SMEM
    {
        const int row   = tid & 63;
        const int kbase = (tid >> 6) * 128;
        const float* stage = (const float*)(smem + SM_PTS);
        float px = stage[row * 3 + 0], py = stage[row * 3 + 1], pz = stage[row * 3 + 2];
        float p2 = px * px + py * py + pz * pz;
        const float4* qt = (const float4*)(smem + SM_QT);
        const float*  ct = (const float*)(smem + SM_CT);
        #pragma unroll 4
        for (int j = 0; j < 16; ++j) {
            float ev[8];
            #pragma unroll
            for (int q = 0; q < 8; ++q) {
                int g = kbase + j * 8 + q;
                float4 qv = qt[g];
                float arg = fmaf(qv.x, px, fmaf(qv.y, py,
                            fmaf(qv.z, pz, fmaf(qv.w, p2, ct[g]))));
                asm("ex2.approx.f32 %0, %1;" : "=f"(ev[q]) : "f"(arg));
            }
            uint4 pk;
            pk.x = pack_h2(ev[0], ev[1]);
            pk.y = pack_h2(ev[2], ev[3]);
            pk.z = pack_h2(ev[4], ev[5]);
            pk.w = pack_h2(ev[6], ev[7]);
            *reinterpret_cast<uint4*>(smem + SM_A + row * A_STRIDE_B + (kbase + j * 8) * 2) = pk;
        }
    }
    __syncthreads();                                         // A visible to all warps

    const int wm = (wid & 1) * 32;        // 2 M-warps
    const int wn = (wid >> 1) * 64;       // 4 N-warps over 256 cols

    for (int cc = 0; cc < 2; ++cc) {
        float acc[2][8][4];
        #pragma unroll
        for (int tm = 0; tm < 2; ++tm)
            #pragma unroll
            for (int tn = 0; tn < 8; ++tn)
                #pragma unroll
                for (int q = 0; q < 4; ++q)
                    acc[tm][tn][q] = 0.0f;

        for (int kidx = 0; kidx < 16; ++kidx) {
            int g = cc * 16 + kidx;
            // single-sync pipeline: wait -> sync -> issue next -> compute
            asm volatile("cp.async.wait_group 0;" ::: "memory");
            __syncthreads();
            if (g < 31) issue_slice(g + 1);

            uint32_t Bb = sbase + ((g & 1) ? SM_B1 : SM_B0);
            int kabs = kidx * 32;
            #pragma unroll
            for (int kk = 0; kk < 2; ++kk) {
                int krow = kk * 16;
                uint32_t a[2][4];
                #pragma unroll
                for (int tm = 0; tm < 2; ++tm) {
                    uint32_t addr = sbase + SM_A + (wm + tm * 16 + (lane & 15)) * A_STRIDE_B
                                    + (kabs + krow + (lane >> 4) * 8) * 2;
                    ldsm_x4(addr, a[tm]);
                }
                uint32_t bf[4][4];
                #pragma unroll
                for (int tn2 = 0; tn2 < 4; ++tn2) {
                    uint32_t addr = Bb + (krow + (lane & 15)) * B_STRIDE
                                    + (wn + tn2 * 16 + (lane >> 4) * 8) * 2;
                    ldsm_x4_t(addr, bf[tn2]);
                }
                #pragma unroll
                for (int tm = 0; tm < 2; ++tm)
                    #pragma unroll
                    for (int tn = 0; tn < 8; ++tn)
                        mma16816(acc[tm][tn], a[tm], &bf[tn >> 1][(tn & 1) * 2]);
            }
        }

        // epilogue: direct v2 STG (quarter-warp = full 32B sector)
        #pragma unroll
        for (int tm = 0; tm < 2; ++tm) {
            int rbase = n0 + wm + tm * 16 + (lane >> 2);
            #pragma unroll
            for (int half = 0; half < 2; ++half) {
                int r = rbase + half * 8;
                if (r < Ntot) {
                    float* op = out + ((size_t)b * Ntot + r) * CDIM
                                + cc * 256 + wn + (lane & 3) * 2;
                    #pragma unroll
                    for (int tn = 0; tn < 8; ++tn) {
                        float2 v = make_float2(acc[tm][tn][half * 2],
                                               acc[tm][tn][half * 2 + 1]);
                        *reinterpret_cast<float2*>(op + tn * 8) = v;
                    }
                }
            }
        }
    }
}

extern "C" void kernel_launch(void* const* d_in, const int* in_sizes, int n_in,
                              void* d_out, int out_size) {
    const float* points = (const float*)d_in[0];
    const float* lat    = (const float*)d_in[1];
    const float* eps    = (const float*)d_in[2];
    float* out = (float*)d_out;

    int B = in_sizes[1] / (G * CDIM);          // 4
    int N = in_sizes[0] / (3 * B);             // 50000

    cudaFuncSetAttribute(rbf_main, cudaFuncAttributeMaxDynamicSharedMemorySize, SM_TOTAL);

    rbf_prep<<<dim3((G * CDIM / 4) / 256, B), 256>>>(lat);
    rbf_main<<<dim3((N + TILE_M - 1) / TILE_M, B), THREADS, SM_TOTAL>>>(points, eps, out, N);
}

// round 7
// speedup vs baseline: 1.2064x; 1.0063x over previous
#include <cuda_runtime.h>
#include <cuda_fp16.h>
#include <stdint.h>

#define G       512
#define CDIM    512
#define TILE_M  64
#define THREADS 256

// ---- SMEM layout (per CTA; 2 CTAs/SM) ----
// A: 64 rows x 1024B, XOR-swizzled chunks (no pad)
#define SM_A       0                       // 65536
// B: 3 stages, each 32 rows x 512B, XOR-swizzled (no pad)
#define SM_BBASE   65536
#define B_STAGE_SZ 16384
// tables overlaid inside stage-2 buffer (dead after A-gen; stage2 written later)
#define SM_QT      (SM_BBASE + 2 * B_STAGE_SZ)            // 98304, 8KB
#define SM_CT      (SM_QT + 8192)                         // 106496, 2KB
#define SM_PTS     (SM_BBASE + 3 * B_STAGE_SZ)            // 114688, 768B
#define SM_TOTAL   (SM_PTS + 768)                         // 115456 (x2 = 230912)

// fp16 image of latents: [b][k][c] row-major
__device__ __align__(16) unsigned char g_Bprep[4ull * G * CDIM * 2];

__device__ __forceinline__ uint32_t cvta_s(const void* p) {
    return (uint32_t)__cvta_generic_to_shared(const_cast<void*>(p));
}

__device__ __forceinline__ uint32_t pack_h2(float lo, float hi) {
    __half2 h = __floats2half2_rn(lo, hi);
    return *reinterpret_cast<uint32_t*>(&h);
}

__device__ __forceinline__ void ldsm_x4(uint32_t addr, uint32_t* r) {
    asm volatile("ldmatrix.sync.aligned.m8n8.x4.shared.b16 {%0,%1,%2,%3}, [%4];"
                 : "=r"(r[0]), "=r"(r[1]), "=r"(r[2]), "=r"(r[3]) : "r"(addr));
}

__device__ __forceinline__ void ldsm_x4_t(uint32_t addr, uint32_t* r) {
    asm volatile("ldmatrix.sync.aligned.m8n8.x4.trans.shared.b16 {%0,%1,%2,%3}, [%4];"
                 : "=r"(r[0]), "=r"(r[1]), "=r"(r[2]), "=r"(r[3]) : "r"(addr));
}

__device__ __forceinline__ void mma16816(float* d, const uint32_t* a, const uint32_t* b) {
    asm volatile(
        "mma.sync.aligned.m16n8k16.row.col.f32.f16.f16.f32 "
        "{%0,%1,%2,%3}, {%4,%5,%6,%7}, {%8,%9}, {%0,%1,%2,%3};"
        : "+f"(d[0]), "+f"(d[1]), "+f"(d[2]), "+f"(d[3])
        : "r"(a[0]), "r"(a[1]), "r"(a[2]), "r"(a[3]), "r"(b[0]), "r"(b[1]));
}

// ---------- prep: elementwise fp32 -> fp16 convert of latents ----------
__global__ void rbf_prep(const float* __restrict__ lat) {
    int b = blockIdx.y;
    int i = blockIdx.x * blockDim.x + threadIdx.x;
    const float4* src = (const float4*)(lat + (size_t)b * G * CDIM);
    uint2* dst = (uint2*)(g_Bprep + (size_t)b * G * CDIM * 2);
    float4 v = src[i];
    uint2 o;
    o.x = pack_h2(v.x, v.y);
    o.y = pack_h2(v.z, v.w);
    dst[i] = o;
}

// ---------- main kernel ----------
__global__ void __launch_bounds__(THREADS, 2)
rbf_main(const float* __restrict__ points, const float* __restrict__ eps,
         float* __restrict__ out, int Ntot)
{
    extern __shared__ __align__(1024) unsigned char smem[];
    const uint32_t sbase = cvta_s(smem);
    const int tid  = threadIdx.x;
    const int wid  = tid >> 5;
    const int lane = tid & 31;
    const int b    = blockIdx.y;
    const int n0   = blockIdx.x * TILE_M;
    const unsigned char* Bsrc = g_Bprep + (size_t)b * (G * CDIM * 2);

    // slice g (0..31): cc = g>>4, kabs = (g&15)*32; 32 rows x 256 cols -> buf g%3
    auto issue_slice = [&](int g) {
        int cc   = g >> 4;
        int kabs = (g & 15) * 32;
        uint32_t dstbase = sbase + SM_BBASE + (uint32_t)(g % 3) * B_STAGE_SZ;
        #pragma unroll
        for (int j = 0; j < 4; ++j) {
            int s  = tid + j * THREADS;                      // 1024 slots: 32 rows x 32 chunks
            int r  = s >> 5;
            int ch = s & 31;
            const unsigned char* src = Bsrc + ((size_t)(kabs + r) * CDIM + cc * 256) * 2 + ch * 16;
            uint32_t dst = dstbase + r * 512 + (uint32_t)((ch ^ (r & 7)) << 4);
            asm volatile("cp.async.cg.shared.global [%0], [%1], 16;" :: "r"(dst), "l"(src));
        }
        asm volatile("cp.async.commit_group;" ::: "memory");
    };

    issue_slice(0);                                          // buf0, overlaps prologue
    issue_slice(1);                                          // buf1

    // stage points
    {
        const float* psrc = points + ((size_t)b * Ntot + n0) * 3;
        int nfl = min(TILE_M, Ntot - n0) * 3;
        float* stage = (float*)(smem + SM_PTS);
        for (int i = tid; i < TILE_M * 3; i += THREADS)
            stage[i] = (i < nfl) ? psrc[i] : 0.0f;
    }

    // per-g tables (live in stage-2 buffer region; dead before slice 2 arrives)
    {
        float4* qt = (float4*)(smem + SM_QT);
        float*  ct = (float*)(smem + SM_CT);
        const float LOG2E = 1.4426950408889634f;
        const float step  = 2.0f / 7.0f;
        for (int g = tid; g < G; g += THREADS) {
            float gx = -1.0f + step * (float)(g >> 6);
            float gy = -1.0f + step * (float)((g >> 3) & 7);
            float gz = -1.0f + step * (float)(g & 7);
            float e  = eps[g];
            float s  = -e * e * LOG2E;
            qt[g] = make_float4(-2.0f * s * gx, -2.0f * s * gy, -2.0f * s * gz, s);
            ct[g] = s * (gx * gx + gy * gy + gz * gz);
        }
    }
    __syncthreads();

    // A-gen: thread -> (row = tid&63, kq = tid>>6), 128 exps -> swizzled fp16 SMEM
    {
        const int row   = tid & 63;
        const int kbase = (tid >> 6) * 128;
        const float* stage = (const float*)(smem + SM_PTS);
        float px = stage[row * 3 + 0], py = stage[row * 3 + 1], pz = stage[row * 3 + 2];
        float p2 = px * px + py * py + pz * pz;
        const float4* qt = (const float4*)(smem + SM_QT);
        const float*  ct = (const float*)(smem + SM_CT);
        const uint32_t arow = sbase + SM_A + (uint32_t)row * 1024;
        const int swz = row & 7;
        #pragma unroll 4
        for (int j = 0; j < 16; ++j) {
            float ev[8];
            #pragma unroll
            for (int q = 0; q < 8; ++q) {
                int g = kbase + j * 8 + q;
                float4 qv = qt[g];
                float arg = fmaf(qv.x, px, fmaf(qv.y, py,
                            fmaf(qv.z, pz, fmaf(qv.w, p2, ct[g]))));
                asm("ex2.approx.f32 %0, %1;" : "=f"(ev[q]) : "f"(arg));
            }
            uint4 pk;
            pk.x = pack_h2(ev[0], ev[1]);
            pk.y = pack_h2(ev[2], ev[3]);
            pk.z = pack_h2(ev[4], ev[5]);
            pk.w = pack_h2(ev[6], ev[7]);
            int cj = (kbase >> 3) + j;
            asm volatile("st.shared.v4.b32 [%0], {%1,%2,%3,%4};"
                         :: "r"(arow + (uint32_t)((cj ^ swz) << 4)),
                            "r"(pk.x), "r"(pk.y), "r"(pk.z), "r"(pk.w));
        }
    }
    __syncthreads();                                         // A + tables done; stage2 now free

    const int wm = (wid & 1) * 32;        // 2 M-warps
    const int wn = (wid >> 1) * 64;       // 4 N-warps over 256 cols

    float acc[2][8][4];
    #pragma unroll
    for (int tm = 0; tm < 2; ++tm)
        #pragma unroll
        for (int tn = 0; tn < 8; ++tn)
            #pragma unroll
            for (int q = 0; q < 4; ++q)
                acc[tm][tn][q] = 0.0f;

    for (int g = 0; g < 32; ++g) {
        // 3-stage ring: wait (slice g ready, <=1 younger pending), sync, issue g+2
        asm volatile("cp.async.wait_group 1;" ::: "memory");
        __syncthreads();
        if (g + 2 < 32) issue_slice(g + 2);

        uint32_t Bb = sbase + SM_BBASE + (uint32_t)(g % 3) * B_STAGE_SZ;
        int kabs = (g & 15) * 32;
        #pragma unroll
        for (int kk = 0; kk < 2; ++kk) {
            int krow = kk * 16;
            uint32_t a[2][4];
            #pragma unroll
            for (int tm = 0; tm < 2; ++tm) {
                int row = wm + tm * 16 + (lane & 15);
                int kglob = kabs + krow + (lane >> 4) * 8;
                uint32_t addr = sbase + SM_A + (uint32_t)row * 1024
                                + (uint32_t)((((kglob >> 3)) ^ (row & 7)) << 4);
                ldsm_x4(addr, a[tm]);
            }
            uint32_t bf[4][4];
            #pragma unroll
            for (int tn2 = 0; tn2 < 4; ++tn2) {
                int rr  = krow + (lane & 15);
                int col = wn + tn2 * 16 + (lane >> 4) * 8;
                uint32_t addr = Bb + (uint32_t)rr * 512
                                + (uint32_t)(((col >> 3) ^ (rr & 7)) << 4);
                ldsm_x4_t(addr, bf[tn2]);
            }
            #pragma unroll
            for (int tm = 0; tm < 2; ++tm)
                #pragma unroll
                for (int tn = 0; tn < 8; ++tn)
                    mma16816(acc[tm][tn], a[tm], &bf[tn >> 1][(tn & 1) * 2]);
        }

        if (g == 15 || g == 31) {
            int cc = g >> 4;
            #pragma unroll
            for (int tm = 0; tm < 2; ++tm) {
                int rbase = n0 + wm + tm * 16 + (lane >> 2);
                #pragma unroll
                for (int half = 0; half < 2; ++half) {
                    int r = rbase + half * 8;
                    if (r < Ntot) {
                        float* op = out + ((size_t)b * Ntot + r) * CDIM
                                    + cc * 256 + wn + (lane & 3) * 2;
                        #pragma unroll
                        for (int tn = 0; tn < 8; ++tn) {
                            float2 v = make_float2(acc[tm][tn][half * 2],
                                                   acc[tm][tn][half * 2 + 1]);
                            *reinterpret_cast<float2*>(op + tn * 8) = v;
                        }
                    }
                }
            }
            if (g == 15) {
                #pragma unroll
                for (int tm = 0; tm < 2; ++tm)
                    #pragma unroll
                    for (int tn = 0; tn < 8; ++tn)
                        #pragma unroll
                        for (int q = 0; q < 4; ++q)
                            acc[tm][tn][q] = 0.0f;
            }
        }
    }
}

extern "C" void kernel_launch(void* const* d_in, const int* in_sizes, int n_in,
                              void* d_out, int out_size) {
    const float* points = (const float*)d_in[0];
    const float* lat    = (const float*)d_in[1];
    const float* eps    = (const float*)d_in[2];
    float* out = (float*)d_out;

    int B = in_sizes[1] / (G * CDIM);          // 4
    int N = in_sizes[0] / (3 * B);             // 50000

    cudaFuncSetAttribute(rbf_main, cudaFuncAttributeMaxDynamicSharedMemorySize, SM_TOTAL);

    rbf_prep<<<dim3((G * CDIM / 4) / 256, B), 256>>>(lat);
    rbf_main<<<dim3((N + TILE_M - 1) / TILE_M, B), THREADS, SM_TOTAL>>>(points, eps, out, N);
}